// round 12
// baseline (speedup 1.0000x reference)
#include <cuda_runtime.h>
#include <math.h>
#include <stdint.h>

#define B_    32
#define N_    197
#define C_    384
#define H_    12
#define HD_   32
#define HID_  36
#define NN_   (197*197)          // 38809
#define ROWS_ (B_*N_)            // 6304
#define MLPH_ 1536
#define EPSF  1e-5f
#define SQ_   0.42044820762685725f   // 32^-0.25
#define CNTD  1241888.0              // B*N*N per-channel BN count
#define XSZ_  (ROWS_*C_)             // 2420736
#define ASZ_  (B_*H_*NN_)            // 14902656
#define EHID_ (B_*HID_*NN_)          // 44707968
#define P_    (B_*NN_)               // 1241888 points

// ------------------- scratch (device globals; allocation-free rule) ---------
__device__ __align__(16) float g_h  [ROWS_*C_];
__device__ __align__(16) float g_q  [B_*H_*N_*HD_];
__device__ __align__(16) float g_k  [B_*H_*N_*HD_];
__device__ __align__(16) float g_v  [B_*H_*N_*HD_];
__device__ __align__(16) float g_attn0[ASZ_];   // a0, plane layout [B][H][NN]
__device__ __align__(16) float g_ai [EHID_];    // conv_exp out, interleaved [B][NN][36]
__device__ __align__(16) float g_bbi[EHID_];    // dw out, interleaved [B][NN][36]
__device__ __align__(16) float g_ci [ASZ_];     // conv_pro out, interleaved [B][NN][12]
__device__ __align__(16) float g_c  [ASZ_];     // z, plane layout [B][H][NN]
__device__ __align__(16) float g_o  [ROWS_*C_];
__device__ __align__(16) float g_x1 [ROWS_*C_];
__device__ __align__(16) float g_h2 [ROWS_*C_];
__device__ __align__(16) float g_m1 [ROWS_*MLPH_];
// fp32 stats (sum | sumsq)
__device__ float g_s1[2*HID_];
__device__ float g_s2[2*HID_];
__device__ float g_s3[2*H_];
__device__ float g_s4[2*H_];
// folded affines (alpha[CH] | beta[CH])
__device__ float g_ab1[2*HID_];
__device__ float g_ab2[2*HID_];
__device__ float g_ab3[2*H_];
__device__ float g_ab4[2*H_];

// ------------------------------- helpers ------------------------------------
__device__ __forceinline__ float wredsum(float v){
    #pragma unroll
    for (int o = 16; o; o >>= 1) v += __shfl_xor_sync(0xffffffffu, v, o);
    return v;
}
__device__ __forceinline__ float wredmax(float v){
    #pragma unroll
    for (int o = 16; o; o >>= 1) v = fmaxf(v, __shfl_xor_sync(0xffffffffu, v, o));
    return v;
}
__device__ __forceinline__ float clamp6(float v){ return fminf(fmaxf(v, 0.f), 6.f); }
__device__ __forceinline__ float gelu_exact(float v){
    return 0.5f * v * (1.f + erff(v * 0.7071067811865476f));
}
__device__ __forceinline__ uint32_t f2tf(float f){
    uint32_t u; asm("cvt.rna.tf32.f32 %0, %1;" : "=r"(u) : "f"(f)); return u;
}
__device__ __forceinline__ uint4 f4tf(float4 v){
    uint4 u;
    u.x = f2tf(v.x); u.y = f2tf(v.y); u.z = f2tf(v.z); u.w = f2tf(v.w);
    return u;
}
__device__ __forceinline__ void mma_tf32(float* c, const uint32_t* a, const uint32_t* b){
    asm volatile("mma.sync.aligned.m16n8k8.row.col.f32.tf32.tf32.f32 "
        "{%0,%1,%2,%3}, {%4,%5,%6,%7}, {%8,%9}, {%0,%1,%2,%3};"
        : "+f"(c[0]), "+f"(c[1]), "+f"(c[2]), "+f"(c[3])
        : "r"(a[0]), "r"(a[1]), "r"(a[2]), "r"(a[3]), "r"(b[0]), "r"(b[1]));
}

// ------------------------------- kernels ------------------------------------
__global__ void k_nop(){}

// layernorm(0.5*in) * g + b; block 0 also zeros stat arrays when zf!=0
__global__ void k_ln(const float* __restrict__ in, const float* __restrict__ g,
                     const float* __restrict__ b, float* __restrict__ out, int zf){
    int row = blockIdx.x;
    if (zf && row == 0){
        int t = threadIdx.x;
        if (t < 2*HID_){ g_s1[t] = 0.f; g_s2[t] = 0.f; }
        if (t < 2*H_)  { g_s3[t] = 0.f; g_s4[t] = 0.f; }
    }
    const float* p = in + (size_t)row * C_;
    int t = threadIdx.x, w = t >> 5, lane = t & 31;
    float y[3], s = 0.f, sq = 0.f;
    #pragma unroll
    for (int i = 0; i < 3; i++){
        y[i] = 0.5f * p[t + i*128];
        s += y[i]; sq += y[i]*y[i];
    }
    s = wredsum(s); sq = wredsum(sq);
    __shared__ float sh[8];
    if (lane == 0){ sh[w] = s; sh[4+w] = sq; }
    __syncthreads();
    s  = sh[0]+sh[1]+sh[2]+sh[3];
    sq = sh[4]+sh[5]+sh[6]+sh[7];
    float mean = s * (1.f/C_);
    float var  = sq * (1.f/C_) - mean*mean;
    float rs = rsqrtf(var + EPSF);
    #pragma unroll
    for (int i = 0; i < 3; i++){
        int c = t + i*128;
        out[(size_t)row*C_ + c] = (y[i]-mean)*rs*g[c] + b[c];
    }
}

// --- 128x64x16 double-buffered TF32 GEMM; smem row-major [row][k16] pad20 ---
// C = A[M,K] @ W[N,K]^T.  8 warps in 4(m) x 2(n); warp tile 32x32 = 2x4 mma.
#define V_QKV  0
#define V_PROJ 1
#define V_FC1  2
#define V_FC2  3
#define KP_ 20

template<int VAR>
__global__ __launch_bounds__(256, 2)
void gemm_k(const float* __restrict__ A, const float* __restrict__ W,
            const float* __restrict__ bias, const float* __restrict__ extra,
            const float* __restrict__ resid, float* __restrict__ out,
            int M, int N, int K){
    __shared__ uint32_t As[2][128][KP_];
    __shared__ uint32_t Bs[2][64][KP_];
    int tid = threadIdx.x;
    int m0 = blockIdx.y * 128, n0 = blockIdx.x * 64;

    int lane = tid & 31, w = tid >> 5;
    int wm = w & 3, wn = w >> 2;          // warp position: 4 x 2
    int g = lane >> 2, tg = lane & 3;     // groupID, thread-in-group

    float acc[2][4][4];
    #pragma unroll
    for (int mt = 0; mt < 2; mt++)
        #pragma unroll
        for (int nt = 0; nt < 4; nt++)
            #pragma unroll
            for (int i = 0; i < 4; i++) acc[mt][nt][i] = 0.f;

    int lrow = tid >> 2;          // 0..63
    int lk   = (tid & 3) * 4;     // 0,4,8,12

    const float* Arow0 = A + (size_t)(m0 + lrow) * K + lk;
    const float* Arow1 = A + (size_t)(m0 + 64 + lrow) * K + lk;
    const float* Brow  = W + (size_t)(n0 + lrow) * K + lk;
    bool va0 = (m0 + lrow) < M;
    bool va1 = (m0 + 64 + lrow) < M;

    float4 pa0, pa1, pb;
    const float4 z4 = make_float4(0.f,0.f,0.f,0.f);

    pa0 = va0 ? *(const float4*)(Arow0) : z4;
    pa1 = va1 ? *(const float4*)(Arow1) : z4;
    pb  = *(const float4*)(Brow);
    *(uint4*)&As[0][lrow][lk]      = f4tf(pa0);
    *(uint4*)&As[0][64+lrow][lk]   = f4tf(pa1);
    *(uint4*)&Bs[0][lrow][lk]      = f4tf(pb);
    __syncthreads();

    int rowA = wm*32 + g;
    int colB = wn*32 + g;
    int nch = K >> 4;
    for (int c = 0; c < nch; c++){
        int s = c & 1;
        if (c + 1 < nch){
            int off = (c + 1) << 4;
            pa0 = va0 ? *(const float4*)(Arow0 + off) : z4;
            pa1 = va1 ? *(const float4*)(Arow1 + off) : z4;
            pb  = *(const float4*)(Brow + off);
        }
        #pragma unroll
        for (int ks = 0; ks < 2; ks++){
            int kb = ks*8;
            uint32_t af[2][4], bf[4][2];
            #pragma unroll
            for (int mt = 0; mt < 2; mt++){
                int r = rowA + mt*16;
                af[mt][0] = As[s][r][kb+tg];
                af[mt][1] = As[s][r+8][kb+tg];
                af[mt][2] = As[s][r][kb+tg+4];
                af[mt][3] = As[s][r+8][kb+tg+4];
            }
            #pragma unroll
            for (int nt = 0; nt < 4; nt++){
                int cb = colB + nt*8;
                bf[nt][0] = Bs[s][cb][kb+tg];
                bf[nt][1] = Bs[s][cb][kb+tg+4];
            }
            #pragma unroll
            for (int mt = 0; mt < 2; mt++)
                #pragma unroll
                for (int nt = 0; nt < 4; nt++)
                    mma_tf32(acc[mt][nt], af[mt], bf[nt]);
        }
        if (c + 1 < nch){
            __syncthreads();
            int d = s ^ 1;
            *(uint4*)&As[d][lrow][lk]    = f4tf(pa0);
            *(uint4*)&As[d][64+lrow][lk] = f4tf(pa1);
            *(uint4*)&Bs[d][lrow][lk]    = f4tf(pb);
            __syncthreads();
        }
    }

    #pragma unroll
    for (int mt = 0; mt < 2; mt++){
        #pragma unroll
        for (int ri = 0; ri < 2; ri++){
            int gm = m0 + wm*32 + mt*16 + g + ri*8;
            if (gm >= M) continue;
            #pragma unroll
            for (int nt = 0; nt < 4; nt++){
                #pragma unroll
                for (int ci = 0; ci < 2; ci++){
                    int gn = n0 + wn*32 + nt*8 + tg*2 + ci;
                    float v = acc[mt][nt][ri*2 + ci];
                    if (VAR == V_QKV){
                        int which = gn / 384, rr = gn % 384;
                        int hh = rr >> 5, dd = rr & 31;
                        int bb = gm / N_, np = gm % N_;
                        int idx = ((bb*H_ + hh)*N_ + np)*HD_ + dd;
                        if (which == 0)      g_q[idx] = v * SQ_;
                        else if (which == 1) g_k[idx] = v * SQ_;
                        else                 g_v[idx] = v;
                    } else if (VAR == V_PROJ){
                        out[(size_t)gm*384 + gn] = resid[(size_t)gm*384 + gn]
                                                 + (v + bias[gn]) * 2.f;
                    } else if (VAR == V_FC1){
                        out[(size_t)gm*MLPH_ + gn] = gelu_exact(v + bias[gn]);
                    } else { // V_FC2
                        out[(size_t)gm*384 + gn] = resid[(size_t)gm*384 + gn]
                                                 + (v + bias[gn]) * extra[gn] * 2.f;
                    }
                }
            }
        }
    }
}

// ----- attention scores + softmax -> g_attn0 planes -------------------------
__global__ __launch_bounds__(256)
void k_attn_softmax(){
    __shared__ float ksh[197][33];
    int bh = blockIdx.y, tile = blockIdx.x;
    const float* kb = g_k + (size_t)bh * N_ * HD_;
    for (int idx = threadIdx.x; idx < N_*HD_; idx += 256)
        ksh[idx >> 5][idx & 31] = kb[idx];
    __syncthreads();
    int w = threadIdx.x >> 5, lane = threadIdx.x & 31;
    int rrow = tile*8 + w;
    if (rrow >= N_) return;
    const float* qrow = g_q + ((size_t)bh * N_ + rrow) * HD_;
    float qr[32];
    #pragma unroll
    for (int d = 0; d < 32; d++) qr[d] = qrow[d];

    float sc[7];
    #pragma unroll
    for (int j = 0; j < 7; j++){
        int m = lane + j*32;
        float a = -1e30f;
        if (m < N_){
            a = 0.f;
            #pragma unroll
            for (int d = 0; d < 32; d++) a += qr[d] * ksh[m][d];
        }
        sc[j] = a;
    }
    float mx = sc[0];
    #pragma unroll
    for (int j = 1; j < 7; j++) mx = fmaxf(mx, sc[j]);
    mx = wredmax(mx);
    float sum = 0.f;
    #pragma unroll
    for (int j = 0; j < 7; j++){
        sc[j] = __expf(sc[j] - mx);
        sum += sc[j];
    }
    sum = wredsum(sum);
    float inv = 1.f / sum;
    float* orow = g_attn0 + ((size_t)bh * N_ + rrow) * N_;
    #pragma unroll
    for (int j = 0; j < 7; j++){
        int m = lane + j*32;
        if (m < N_) orow[m] = sc[j] * inv;
    }
}

// ---- conv_exp 12->36: attn0 planes -> g_ai interleaved (no stats) ----------
__global__ __launch_bounds__(256, 2)
void k_conv_exp(const float* __restrict__ wexp){
    __shared__ float wsh[HID_*H_];
    for (int i = threadIdx.x; i < HID_*H_; i += 256) wsh[i] = wexp[i];
    __syncthreads();
    for (int p = blockIdx.x*256 + threadIdx.x; p < P_; p += gridDim.x*256){
        int b = p / NN_, pp = p - b*NN_;
        const float* in = g_attn0 + (size_t)b*H_*NN_ + pp;
        float av[H_];
        #pragma unroll
        for (int i = 0; i < H_; i++) av[i] = in[(size_t)i*NN_];
        float4* op = (float4*)(g_ai + (size_t)p*HID_);
        #pragma unroll
        for (int og = 0; og < 9; og++){
            float4 a4 = make_float4(0.f,0.f,0.f,0.f);
            #pragma unroll
            for (int i = 0; i < H_; i++){
                a4.x += wsh[(og*4+0)*H_ + i] * av[i];
                a4.y += wsh[(og*4+1)*H_ + i] * av[i];
                a4.z += wsh[(og*4+2)*H_ + i] * av[i];
                a4.w += wsh[(og*4+3)*H_ + i] * av[i];
            }
            op[og] = a4;
        }
    }
}

// ---- streaming per-channel stats over interleaved tensor -------------------
template<int CH>
__global__ void k_stats(const float4* __restrict__ in, float* __restrict__ sums){
    const int G = CH/4;
    int t = threadIdx.x;
    float4 s = make_float4(0.f,0.f,0.f,0.f);
    float4 q = make_float4(0.f,0.f,0.f,0.f);
    int nf4 = P_ * G;
    for (int f = blockIdx.x*blockDim.x + t; f < nf4; f += gridDim.x*blockDim.x){
        float4 v = in[f];
        s.x += v.x; s.y += v.y; s.z += v.z; s.w += v.w;
        q.x += v.x*v.x; q.y += v.y*v.y; q.z += v.z*v.z; q.w += v.w*v.w;
    }
    __shared__ float red[2*CH];
    if (t < 2*CH) red[t] = 0.f;
    __syncthreads();
    int g = (t % G) * 4;
    atomicAdd(&red[g+0], s.x); atomicAdd(&red[g+1], s.y);
    atomicAdd(&red[g+2], s.z); atomicAdd(&red[g+3], s.w);
    atomicAdd(&red[CH+g+0], q.x); atomicAdd(&red[CH+g+1], q.y);
    atomicAdd(&red[CH+g+2], q.z); atomicAdd(&red[CH+g+3], q.w);
    __syncthreads();
    if (t < 2*CH) atomicAdd(&sums[t], red[t]);
}

// finalize a BN (NCH channels): alpha = g/sqrt(var+eps), beta = b - mean*alpha
template<int NCH>
__global__ void k_fin_bn(const float* __restrict__ gg, const float* __restrict__ bb,
                         const float* __restrict__ sums, float* __restrict__ ab){
    int t = threadIdx.x;
    if (t < NCH){
        double m   = (double)sums[t] / CNTD;
        double var = (double)sums[NCH+t] / CNTD - m*m;
        double al  = (double)gg[t] / sqrt(var + 1e-5);
        ab[t]       = (float)al;
        ab[NCH + t] = (float)((double)bb[t] - m*al);
    }
}

// ---- dw 3x3 over interleaved tensors, all 36 ch per tile (bn1 on load) -----
__global__ __launch_bounds__(256)
void k_dw(const float* __restrict__ dww){
    extern __shared__ float dsh[];          // [10][34][37]
    __shared__ float wsh[HID_*9];
    __shared__ float absh[2*HID_];
    int tile = blockIdx.x, b = blockIdx.y;
    int x0 = (tile % 7) * 32, y0 = (tile / 7) * 8;
    int t = threadIdx.x;
    for (int i = t; i < HID_*9; i += 256) wsh[i] = dww[i];
    if (t < 2*HID_) absh[t] = g_ab1[t];
    __syncthreads();
    for (int idx = t; idx < 10*34*HID_; idx += 256){
        int iy = idx / (34*HID_);
        int r  = idx - iy*(34*HID_);
        int ix = r / HID_, ch = r - ix*HID_;
        int gy = y0 + iy - 1, gx = x0 + ix - 1;
        float v = 0.f;
        if (gy >= 0 && gy < N_ && gx >= 0 && gx < N_)
            v = clamp6(absh[ch] * g_ai[((size_t)b*NN_ + gy*N_ + gx)*HID_ + ch]
                       + absh[HID_+ch]);
        dsh[(iy*34 + ix)*37 + ch] = v;
    }
    __syncthreads();
    int lx = t & 31, ly = t >> 5;
    int gy = y0 + ly, gx = x0 + lx;
    if (gy >= N_ || gx >= N_) return;
    float4* op = (float4*)(g_bbi + ((size_t)b*NN_ + gy*N_ + gx)*HID_);
    #pragma unroll
    for (int chg = 0; chg < 9; chg++){
        float4 o4;
        float* po = (float*)&o4;
        #pragma unroll
        for (int j = 0; j < 4; j++){
            int ch = chg*4 + j;
            float acc = 0.f;
            #pragma unroll
            for (int ky = 0; ky < 3; ky++)
                #pragma unroll
                for (int kx = 0; kx < 3; kx++)
                    acc += wsh[ch*9 + ky*3 + kx] *
                           dsh[((ly+ky)*34 + lx+kx)*37 + ch];
            po[j] = acc;
        }
        op[chg] = o4;
    }
}

// ---- conv_pro 36->12 (bn2 on load): g_bbi -> g_ci + bn3 stats fused --------
__global__ __launch_bounds__(256)
void k_conv_pro(const float* __restrict__ wpro){
    __shared__ float wsh[H_*HID_];
    __shared__ float absh[2*HID_];
    __shared__ float red[2*H_];
    int t = threadIdx.x;
    for (int i = t; i < H_*HID_; i += 256) wsh[i] = wpro[i];
    if (t < 2*HID_) absh[t] = g_ab2[t];
    if (t < 2*H_) red[t] = 0.f;
    __syncthreads();
    float s[H_], q[H_];
    #pragma unroll
    for (int o = 0; o < H_; o++){ s[o] = 0.f; q[o] = 0.f; }
    for (int p = blockIdx.x*256 + t; p < P_; p += gridDim.x*256){
        const float4* in = (const float4*)(g_bbi + (size_t)p*HID_);
        float acc[H_];
        #pragma unroll
        for (int o = 0; o < H_; o++) acc[o] = 0.f;
        #pragma unroll
        for (int ig = 0; ig < 9; ig++){
            float4 v4 = in[ig];
            float vv[4];
            vv[0] = clamp6(absh[ig*4+0]*v4.x + absh[HID_+ig*4+0]);
            vv[1] = clamp6(absh[ig*4+1]*v4.y + absh[HID_+ig*4+1]);
            vv[2] = clamp6(absh[ig*4+2]*v4.z + absh[HID_+ig*4+2]);
            vv[3] = clamp6(absh[ig*4+3]*v4.w + absh[HID_+ig*4+3]);
            #pragma unroll
            for (int o = 0; o < H_; o++){
                acc[o] += wsh[o*HID_ + ig*4+0]*vv[0] + wsh[o*HID_ + ig*4+1]*vv[1]
                        + wsh[o*HID_ + ig*4+2]*vv[2] + wsh[o*HID_ + ig*4+3]*vv[3];
            }
        }
        float4* op = (float4*)(g_ci + (size_t)p*H_);
        op[0] = make_float4(acc[0], acc[1], acc[2],  acc[3]);
        op[1] = make_float4(acc[4], acc[5], acc[6],  acc[7]);
        op[2] = make_float4(acc[8], acc[9], acc[10], acc[11]);
        #pragma unroll
        for (int o = 0; o < H_; o++){ s[o] += acc[o]; q[o] += acc[o]*acc[o]; }
    }
    int lane = t & 31;
    #pragma unroll
    for (int o = 0; o < H_; o++){
        float ws = wredsum(s[o]), wq = wredsum(q[o]);
        if (lane == 0){
            atomicAdd(&red[o],    ws);
            atomicAdd(&red[H_+o], wq);
        }
    }
    __syncthreads();
    if (t < 2*H_) atomicAdd(&g_s3[t], red[t]);
}

// ---- z = bn3(c) + a0 -> g_c planes, + z stats ------------------------------
__global__ __launch_bounds__(256)
void k_z(){
    __shared__ float absh[2*H_];
    __shared__ float red[2*H_];
    int t = threadIdx.x;
    if (t < 2*H_){ absh[t] = g_ab3[t]; red[t] = 0.f; }
    __syncthreads();
    float s[H_], q[H_];
    #pragma unroll
    for (int o = 0; o < H_; o++){ s[o] = 0.f; q[o] = 0.f; }
    for (int p = blockIdx.x*256 + t; p < P_; p += gridDim.x*256){
        int b = p / NN_, pp = p - b*NN_;
        const float* cin = g_ci + (size_t)p*H_;
        const float* a0  = g_attn0 + (size_t)b*H_*NN_ + pp;
        float* zo = g_c + (size_t)b*H_*NN_ + pp;
        #pragma unroll
        for (int ch = 0; ch < H_; ch++){
            float z = absh[ch]*cin[ch] + absh[H_+ch] + a0[(size_t)ch*NN_];
            zo[(size_t)ch*NN_] = z;
            s[ch] += z; q[ch] += z*z;
        }
    }
    int lane = t & 31;
    #pragma unroll
    for (int ch = 0; ch < H_; ch++){
        float ws = wredsum(s[ch]), wq = wredsum(q[ch]);
        if (lane == 0){
            atomicAdd(&red[ch],     ws);
            atomicAdd(&red[H_+ch],  wq);
        }
    }
    __syncthreads();
    if (t < 2*H_) atomicAdd(&g_s4[t], red[t]);
}

// --- attn @ v (abn affine inline); also writes final attn into d_out --------
__global__ __launch_bounds__(256)
void k_av(float* __restrict__ outattn){
    __shared__ float vsh[197][32];
    __shared__ float ash[8][197];
    int bh = blockIdx.y, tile = blockIdx.x;
    int ch = bh % H_;
    float al = g_ab4[ch], be = g_ab4[H_+ch];
    const float* vb = g_v + (size_t)bh * N_ * HD_;
    for (int idx = threadIdx.x; idx < N_*HD_; idx += 256)
        vsh[idx >> 5][idx & 31] = vb[idx];
    __syncthreads();
    int w = threadIdx.x >> 5, lane = threadIdx.x & 31;
    int rrow = tile*8 + w;
    if (rrow >= N_) return;
    size_t rbase = ((size_t)bh * N_ + rrow) * N_;
    const float* arow = g_c + rbase;
    if (outattn){
        float* orow = outattn + rbase;
        for (int m = lane; m < N_; m += 32){
            float v = al * arow[m] + be;
            ash[w][m] = v;
            orow[m] = v;
        }
    } else {
        for (int m = lane; m < N_; m += 32) ash[w][m] = al * arow[m] + be;
    }
    __syncwarp();
    float acc = 0.f;
    #pragma unroll 8
    for (int m = 0; m < N_; m++)
        acc += ash[w][m] * vsh[m][lane];
    int b = bh / H_, h = bh % H_;
    g_o[((size_t)b*N_ + rrow)*C_ + h*HD_ + lane] = acc;
}

// ------------------------------- launch -------------------------------------
extern "C" void kernel_launch(void* const* d_in, const int* in_sizes, int n_in,
                              void* d_out, int out_size){
    const float* x        = (const float*)d_in[0];
    const float* ln1_g    = (const float*)d_in[1];
    const float* ln1_b    = (const float*)d_in[2];
    const float* qkv_w    = (const float*)d_in[3];
    const float* conv_exp = (const float*)d_in[4];
    const float* bn1_g    = (const float*)d_in[5];
    const float* bn1_b    = (const float*)d_in[6];
    const float* dw_w     = (const float*)d_in[7];
    const float* bn2_g    = (const float*)d_in[8];
    const float* bn2_b    = (const float*)d_in[9];
    const float* conv_pro = (const float*)d_in[10];
    const float* bn3_g    = (const float*)d_in[11];
    const float* bn3_b    = (const float*)d_in[12];
    const float* abn_g    = (const float*)d_in[13];
    const float* abn_b    = (const float*)d_in[14];
    const float* proj_w   = (const float*)d_in[15];
    const float* proj_b   = (const float*)d_in[16];
    const float* ln2_g    = (const float*)d_in[17];
    const float* ln2_b    = (const float*)d_in[18];
    const float* fc1_w    = (const float*)d_in[19];
    const float* fc1_b    = (const float*)d_in[20];
    const float* fc2_w    = (const float*)d_in[21];
    const float* fc2_b    = (const float*)d_in[22];
    const float* scale_ch = (const float*)d_in[23];

    float* out      = (float*)d_out;
    float* out_attn = (out_size >= XSZ_ + ASZ_) ? (out + XSZ_) : nullptr;

    float *p_h, *p_o, *p_x1, *p_h2, *p_m1, *p_ai, *p_bbi, *p_ci;
    float *p_s1, *p_s2, *p_s3, *p_s4, *p_ab1, *p_ab2, *p_ab3, *p_ab4;
    cudaGetSymbolAddress((void**)&p_h,   g_h);
    cudaGetSymbolAddress((void**)&p_o,   g_o);
    cudaGetSymbolAddress((void**)&p_x1,  g_x1);
    cudaGetSymbolAddress((void**)&p_h2,  g_h2);
    cudaGetSymbolAddress((void**)&p_m1,  g_m1);
    cudaGetSymbolAddress((void**)&p_ai,  g_ai);
    cudaGetSymbolAddress((void**)&p_bbi, g_bbi);
    cudaGetSymbolAddress((void**)&p_ci,  g_ci);
    cudaGetSymbolAddress((void**)&p_s1,  g_s1);
    cudaGetSymbolAddress((void**)&p_s2,  g_s2);
    cudaGetSymbolAddress((void**)&p_s3,  g_s3);
    cudaGetSymbolAddress((void**)&p_s4,  g_s4);
    cudaGetSymbolAddress((void**)&p_ab1, g_ab1);
    cudaGetSymbolAddress((void**)&p_ab2, g_ab2);
    cudaGetSymbolAddress((void**)&p_ab3, g_ab3);
    cudaGetSymbolAddress((void**)&p_ab4, g_ab4);

    const int DW_SMEM = 10*34*37*4;
    cudaFuncSetAttribute(k_dw, cudaFuncAttributeMaxDynamicSharedMemorySize, DW_SMEM);

    // slots 1-3 cheap, so the ncu capture slot (4th launch) = QKV mma GEMM
    k_ln<<<ROWS_, 128>>>(x, ln1_g, ln1_b, p_h, 1);
    k_nop<<<1, 32>>>();
    k_nop<<<1, 32>>>();
    gemm_k<V_QKV><<<dim3(18, 50), 256>>>(p_h, qkv_w, nullptr, nullptr, nullptr,
                                         nullptr, ROWS_, 1152, 384);
    k_attn_softmax<<<dim3(25, B_*H_), 256>>>();
    // DLA refine
    k_conv_exp<<<1184, 256>>>(conv_exp);
    k_stats<HID_><<<1184, 288>>>((const float4*)p_ai, p_s1);
    k_fin_bn<HID_><<<1, 64>>>(bn1_g, bn1_b, p_s1, p_ab1);
    k_dw<<<dim3(175, B_), 256, DW_SMEM>>>(dw_w);
    k_stats<HID_><<<1184, 288>>>((const float4*)p_bbi, p_s2);
    k_fin_bn<HID_><<<1, 64>>>(bn2_g, bn2_b, p_s2, p_ab2);
    k_conv_pro<<<1184, 256>>>(conv_pro);           // bn3 stats fused
    k_fin_bn<H_><<<1, 32>>>(bn3_g, bn3_b, p_s3, p_ab3);
    k_z<<<1184, 256>>>();
    k_fin_bn<H_><<<1, 32>>>(abn_g, abn_b, p_s4, p_ab4);
    // attn @ v (abn inline, writes out_attn), proj + residual
    k_av<<<dim3(25, B_*H_), 256>>>(out_attn);
    gemm_k<V_PROJ><<<dim3(6, 50), 256>>>(p_o, proj_w, proj_b, nullptr, x,
                                         p_x1, ROWS_, 384, 384);
    // MLP
    k_ln<<<ROWS_, 128>>>(p_x1, ln2_g, ln2_b, p_h2, 0);
    gemm_k<V_FC1><<<dim3(24, 50), 256>>>(p_h2, fc1_w, fc1_b, nullptr, nullptr,
                                         p_m1, ROWS_, MLPH_, 384);
    gemm_k<V_FC2><<<dim3(6, 50), 256>>>(p_m1, fc2_w, fc2_b, scale_ch, p_x1,
                                        out, ROWS_, 384, MLPH_);
}

// round 13
// speedup vs baseline: 1.1834x; 1.1834x over previous
#include <cuda_runtime.h>
#include <math.h>
#include <stdint.h>

#define B_    32
#define N_    197
#define C_    384
#define H_    12
#define HD_   32
#define HID_  36
#define NN_   (197*197)          // 38809
#define ROWS_ (B_*N_)            // 6304
#define MLPH_ 1536
#define EPSF  1e-5f
#define SQ_   0.42044820762685725f   // 32^-0.25
#define CNTD  1241888.0              // B*N*N per-channel BN count
#define XSZ_  (ROWS_*C_)             // 2420736
#define ASZ_  (B_*H_*NN_)            // 14902656
#define EHID_ (B_*HID_*NN_)          // 44707968
#define P_    (B_*NN_)               // 1241888 points
#define NCOV_ 78

// ------------------- scratch (device globals; allocation-free rule) ---------
__device__ __align__(16) float g_h  [ROWS_*C_];
__device__ __align__(16) float g_q  [B_*H_*N_*HD_];
__device__ __align__(16) float g_k  [B_*H_*N_*HD_];
__device__ __align__(16) float g_v  [B_*H_*N_*HD_];
__device__ __align__(16) float g_attn0[ASZ_];   // a0, plane layout [B][H][NN]
__device__ __align__(16) float g_bbi[EHID_];    // dw out, interleaved [B][NN][36]
__device__ __align__(16) float g_ci [ASZ_];     // conv_pro out, interleaved [B][NN][12]
__device__ __align__(16) float g_c  [ASZ_];     // z, plane layout [B][H][NN]
__device__ __align__(16) float g_o  [ROWS_*C_];
__device__ __align__(16) float g_x1 [ROWS_*C_];
__device__ __align__(16) float g_h2 [ROWS_*C_];
__device__ __align__(16) float g_m1 [ROWS_*MLPH_];
// stats
__device__ float g_cov[NCOV_];   // upper-tri second-moment of attn0 channels
__device__ float g_s2[2*HID_];
__device__ float g_s3[2*H_];
__device__ float g_s4[2*H_];
// folded affines (alpha[CH] | beta[CH])
__device__ float g_ab1[2*HID_];
__device__ float g_ab2[2*HID_];
__device__ float g_ab3[2*H_];
__device__ float g_ab4[2*H_];

// ------------------------------- helpers ------------------------------------
__device__ __forceinline__ float wredsum(float v){
    #pragma unroll
    for (int o = 16; o; o >>= 1) v += __shfl_xor_sync(0xffffffffu, v, o);
    return v;
}
__device__ __forceinline__ float wredmax(float v){
    #pragma unroll
    for (int o = 16; o; o >>= 1) v = fmaxf(v, __shfl_xor_sync(0xffffffffu, v, o));
    return v;
}
__device__ __forceinline__ float clamp6(float v){ return fminf(fmaxf(v, 0.f), 6.f); }
__device__ __forceinline__ float gelu_exact(float v){
    return 0.5f * v * (1.f + erff(v * 0.7071067811865476f));
}
__device__ __forceinline__ uint32_t f2tf(float f){
    uint32_t u; asm("cvt.rna.tf32.f32 %0, %1;" : "=r"(u) : "f"(f)); return u;
}
__device__ __forceinline__ uint4 f4tf(float4 v){
    uint4 u;
    u.x = f2tf(v.x); u.y = f2tf(v.y); u.z = f2tf(v.z); u.w = f2tf(v.w);
    return u;
}
__device__ __forceinline__ void mma_tf32(float* c, const uint32_t* a, const uint32_t* b){
    asm volatile("mma.sync.aligned.m16n8k8.row.col.f32.tf32.tf32.f32 "
        "{%0,%1,%2,%3}, {%4,%5,%6,%7}, {%8,%9}, {%0,%1,%2,%3};"
        : "+f"(c[0]), "+f"(c[1]), "+f"(c[2]), "+f"(c[3])
        : "r"(a[0]), "r"(a[1]), "r"(a[2]), "r"(a[3]), "r"(b[0]), "r"(b[1]));
}

// ------------------------------- kernels ------------------------------------
__global__ void k_nop(){}

// layernorm(0.5*in) * g + b; block 0 also zeros stat arrays when zf!=0
__global__ void k_ln(const float* __restrict__ in, const float* __restrict__ g,
                     const float* __restrict__ b, float* __restrict__ out, int zf){
    int row = blockIdx.x;
    if (zf && row == 0){
        int t = threadIdx.x;
        if (t < NCOV_)  g_cov[t] = 0.f;
        if (t < 2*HID_) g_s2[t] = 0.f;
        if (t < 2*H_)  { g_s3[t] = 0.f; g_s4[t] = 0.f; }
    }
    const float* p = in + (size_t)row * C_;
    int t = threadIdx.x, w = t >> 5, lane = t & 31;
    float y[3], s = 0.f, sq = 0.f;
    #pragma unroll
    for (int i = 0; i < 3; i++){
        y[i] = 0.5f * p[t + i*128];
        s += y[i]; sq += y[i]*y[i];
    }
    s = wredsum(s); sq = wredsum(sq);
    __shared__ float sh[8];
    if (lane == 0){ sh[w] = s; sh[4+w] = sq; }
    __syncthreads();
    s  = sh[0]+sh[1]+sh[2]+sh[3];
    sq = sh[4]+sh[5]+sh[6]+sh[7];
    float mean = s * (1.f/C_);
    float var  = sq * (1.f/C_) - mean*mean;
    float rs = rsqrtf(var + EPSF);
    #pragma unroll
    for (int i = 0; i < 3; i++){
        int c = t + i*128;
        out[(size_t)row*C_ + c] = (y[i]-mean)*rs*g[c] + b[c];
    }
}

// --- 128x64x16 double-buffered TF32 GEMM; smem row-major [row][k16] pad20 ---
#define V_QKV  0
#define V_PROJ 1
#define V_FC1  2
#define V_FC2  3
#define KP_ 20

template<int VAR>
__global__ __launch_bounds__(256, 2)
void gemm_k(const float* __restrict__ A, const float* __restrict__ W,
            const float* __restrict__ bias, const float* __restrict__ extra,
            const float* __restrict__ resid, float* __restrict__ out,
            int M, int N, int K){
    __shared__ uint32_t As[2][128][KP_];
    __shared__ uint32_t Bs[2][64][KP_];
    int tid = threadIdx.x;
    int m0 = blockIdx.y * 128, n0 = blockIdx.x * 64;

    int lane = tid & 31, w = tid >> 5;
    int wm = w & 3, wn = w >> 2;
    int g = lane >> 2, tg = lane & 3;

    float acc[2][4][4];
    #pragma unroll
    for (int mt = 0; mt < 2; mt++)
        #pragma unroll
        for (int nt = 0; nt < 4; nt++)
            #pragma unroll
            for (int i = 0; i < 4; i++) acc[mt][nt][i] = 0.f;

    int lrow = tid >> 2;
    int lk   = (tid & 3) * 4;

    const float* Arow0 = A + (size_t)(m0 + lrow) * K + lk;
    const float* Arow1 = A + (size_t)(m0 + 64 + lrow) * K + lk;
    const float* Brow  = W + (size_t)(n0 + lrow) * K + lk;
    bool va0 = (m0 + lrow) < M;
    bool va1 = (m0 + 64 + lrow) < M;

    float4 pa0, pa1, pb;
    const float4 z4 = make_float4(0.f,0.f,0.f,0.f);

    pa0 = va0 ? *(const float4*)(Arow0) : z4;
    pa1 = va1 ? *(const float4*)(Arow1) : z4;
    pb  = *(const float4*)(Brow);
    *(uint4*)&As[0][lrow][lk]      = f4tf(pa0);
    *(uint4*)&As[0][64+lrow][lk]   = f4tf(pa1);
    *(uint4*)&Bs[0][lrow][lk]      = f4tf(pb);
    __syncthreads();

    int rowA = wm*32 + g;
    int colB = wn*32 + g;
    int nch = K >> 4;
    for (int c = 0; c < nch; c++){
        int s = c & 1;
        if (c + 1 < nch){
            int off = (c + 1) << 4;
            pa0 = va0 ? *(const float4*)(Arow0 + off) : z4;
            pa1 = va1 ? *(const float4*)(Arow1 + off) : z4;
            pb  = *(const float4*)(Brow + off);
        }
        #pragma unroll
        for (int ks = 0; ks < 2; ks++){
            int kb = ks*8;
            uint32_t af[2][4], bf[4][2];
            #pragma unroll
            for (int mt = 0; mt < 2; mt++){
                int r = rowA + mt*16;
                af[mt][0] = As[s][r][kb+tg];
                af[mt][1] = As[s][r+8][kb+tg];
                af[mt][2] = As[s][r][kb+tg+4];
                af[mt][3] = As[s][r+8][kb+tg+4];
            }
            #pragma unroll
            for (int nt = 0; nt < 4; nt++){
                int cb = colB + nt*8;
                bf[nt][0] = Bs[s][cb][kb+tg];
                bf[nt][1] = Bs[s][cb][kb+tg+4];
            }
            #pragma unroll
            for (int mt = 0; mt < 2; mt++)
                #pragma unroll
                for (int nt = 0; nt < 4; nt++)
                    mma_tf32(acc[mt][nt], af[mt], bf[nt]);
        }
        if (c + 1 < nch){
            __syncthreads();
            int d = s ^ 1;
            *(uint4*)&As[d][lrow][lk]    = f4tf(pa0);
            *(uint4*)&As[d][64+lrow][lk] = f4tf(pa1);
            *(uint4*)&Bs[d][lrow][lk]    = f4tf(pb);
            __syncthreads();
        }
    }

    #pragma unroll
    for (int mt = 0; mt < 2; mt++){
        #pragma unroll
        for (int ri = 0; ri < 2; ri++){
            int gm = m0 + wm*32 + mt*16 + g + ri*8;
            if (gm >= M) continue;
            #pragma unroll
            for (int nt = 0; nt < 4; nt++){
                #pragma unroll
                for (int ci = 0; ci < 2; ci++){
                    int gn = n0 + wn*32 + nt*8 + tg*2 + ci;
                    float v = acc[mt][nt][ri*2 + ci];
                    if (VAR == V_QKV){
                        int which = gn / 384, rr = gn % 384;
                        int hh = rr >> 5, dd = rr & 31;
                        int bb = gm / N_, np = gm % N_;
                        int idx = ((bb*H_ + hh)*N_ + np)*HD_ + dd;
                        if (which == 0)      g_q[idx] = v * SQ_;
                        else if (which == 1) g_k[idx] = v * SQ_;
                        else                 g_v[idx] = v;
                    } else if (VAR == V_PROJ){
                        out[(size_t)gm*384 + gn] = resid[(size_t)gm*384 + gn]
                                                 + (v + bias[gn]) * 2.f;
                    } else if (VAR == V_FC1){
                        out[(size_t)gm*MLPH_ + gn] = gelu_exact(v + bias[gn]);
                    } else { // V_FC2
                        out[(size_t)gm*384 + gn] = resid[(size_t)gm*384 + gn]
                                                 + (v + bias[gn]) * extra[gn] * 2.f;
                    }
                }
            }
        }
    }
}

// ----- attention scores + softmax -> g_attn0 planes -------------------------
__global__ __launch_bounds__(256)
void k_attn_softmax(){
    __shared__ float ksh[197][33];
    int bh = blockIdx.y, tile = blockIdx.x;
    const float* kb = g_k + (size_t)bh * N_ * HD_;
    for (int idx = threadIdx.x; idx < N_*HD_; idx += 256)
        ksh[idx >> 5][idx & 31] = kb[idx];
    __syncthreads();
    int w = threadIdx.x >> 5, lane = threadIdx.x & 31;
    int rrow = tile*8 + w;
    if (rrow >= N_) return;
    const float* qrow = g_q + ((size_t)bh * N_ + rrow) * HD_;
    float qr[32];
    #pragma unroll
    for (int d = 0; d < 32; d++) qr[d] = qrow[d];

    float sc[7];
    #pragma unroll
    for (int j = 0; j < 7; j++){
        int m = lane + j*32;
        float a = -1e30f;
        if (m < N_){
            a = 0.f;
            #pragma unroll
            for (int d = 0; d < 32; d++) a += qr[d] * ksh[m][d];
        }
        sc[j] = a;
    }
    float mx = sc[0];
    #pragma unroll
    for (int j = 1; j < 7; j++) mx = fmaxf(mx, sc[j]);
    mx = wredmax(mx);
    float sum = 0.f;
    #pragma unroll
    for (int j = 0; j < 7; j++){
        sc[j] = __expf(sc[j] - mx);
        sum += sc[j];
    }
    sum = wredsum(sum);
    float inv = 1.f / sum;
    float* orow = g_attn0 + ((size_t)bh * N_ + rrow) * N_;
    #pragma unroll
    for (int j = 0; j < 7; j++){
        int m = lane + j*32;
        if (m < N_) orow[m] = sc[j] * inv;
    }
}

// ---- second-moment matrix of attn0 channels (78 upper-tri entries) ---------
__global__ __launch_bounds__(256, 2)
void k_cov(){
    float cv[NCOV_];
    #pragma unroll
    for (int u = 0; u < NCOV_; u++) cv[u] = 0.f;
    for (int p = blockIdx.x*256 + threadIdx.x; p < P_; p += gridDim.x*256){
        int b = p / NN_, pp = p - b*NN_;
        const float* in = g_attn0 + (size_t)b*H_*NN_ + pp;
        float av[H_];
        #pragma unroll
        for (int i = 0; i < H_; i++) av[i] = in[(size_t)i*NN_];
        int u = 0;
        #pragma unroll
        for (int i = 0; i < H_; i++)
            #pragma unroll
            for (int j = i; j < H_; j++)
                cv[u++] += av[i]*av[j];
    }
    __shared__ float red[NCOV_];
    int t = threadIdx.x, lane = t & 31;
    if (t < NCOV_) red[t] = 0.f;
    __syncthreads();
    #pragma unroll
    for (int u = 0; u < NCOV_; u++){
        float v = wredsum(cv[u]);
        if (lane == 0) atomicAdd(&red[u], v);
    }
    __syncthreads();
    if (t < NCOV_) atomicAdd(&g_cov[t], red[t]);
}

// ---- analytic bn1 finalize: s = W·(B·N), q = W Σ W^T -----------------------
__global__ void k_fin_bn1(const float* __restrict__ wexp,
                          const float* __restrict__ g1,
                          const float* __restrict__ b1){
    int o = threadIdx.x;
    if (o < HID_){
        double s = 0.0, q = 0.0;
        for (int i = 0; i < H_; i++){
            double wi = (double)wexp[o*H_ + i];
            s += wi;
            for (int j = 0; j < H_; j++){
                int a = i < j ? i : j, bj = i < j ? j : i;
                int idx = a*H_ - (a*(a-1))/2 + (bj - a);
                q += wi * (double)wexp[o*H_ + j] * (double)g_cov[idx];
            }
        }
        s *= (double)ROWS_;
        double m   = s / CNTD;
        double var = q / CNTD - m*m;
        double al  = (double)g1[o] / sqrt(var + 1e-5);
        g_ab1[o]        = (float)al;
        g_ab1[HID_ + o] = (float)((double)b1[o] - m*al);
    }
}

// ---- streaming per-channel stats over interleaved tensor -------------------
template<int CH>
__global__ void k_stats(const float4* __restrict__ in, float* __restrict__ sums){
    const int G = CH/4;
    int t = threadIdx.x;
    float4 s = make_float4(0.f,0.f,0.f,0.f);
    float4 q = make_float4(0.f,0.f,0.f,0.f);
    int nf4 = P_ * G;
    for (int f = blockIdx.x*blockDim.x + t; f < nf4; f += gridDim.x*blockDim.x){
        float4 v = in[f];
        s.x += v.x; s.y += v.y; s.z += v.z; s.w += v.w;
        q.x += v.x*v.x; q.y += v.y*v.y; q.z += v.z*v.z; q.w += v.w*v.w;
    }
    __shared__ float red[2*CH];
    if (t < 2*CH) red[t] = 0.f;
    __syncthreads();
    int g = (t % G) * 4;
    atomicAdd(&red[g+0], s.x); atomicAdd(&red[g+1], s.y);
    atomicAdd(&red[g+2], s.z); atomicAdd(&red[g+3], s.w);
    atomicAdd(&red[CH+g+0], q.x); atomicAdd(&red[CH+g+1], q.y);
    atomicAdd(&red[CH+g+2], q.z); atomicAdd(&red[CH+g+3], q.w);
    __syncthreads();
    if (t < 2*CH) atomicAdd(&sums[t], red[t]);
}

// finalize a BN (NCH channels)
template<int NCH>
__global__ void k_fin_bn(const float* __restrict__ gg, const float* __restrict__ bb,
                         const float* __restrict__ sums, float* __restrict__ ab){
    int t = threadIdx.x;
    if (t < NCH){
        double m   = (double)sums[t] / CNTD;
        double var = (double)sums[NCH+t] / CNTD - m*m;
        double al  = (double)gg[t] / sqrt(var + 1e-5);
        ab[t]       = (float)al;
        ab[NCH + t] = (float)((double)bb[t] - m*al);
    }
}

// ---- dw 3x3; conv_exp + bn1 + relu6 computed on the fly in halo load -------
__global__ __launch_bounds__(256)
void k_dw(const float* __restrict__ dww, const float* __restrict__ wexp){
    extern __shared__ float dsh[];          // [10*34][37]
    __shared__ float wsh[HID_*9];
    __shared__ float wexp_sh[HID_*H_];
    __shared__ float absh[2*HID_];
    int tile = blockIdx.x, b = blockIdx.y;
    int x0 = (tile % 7) * 32, y0 = (tile / 7) * 8;
    int t = threadIdx.x;
    for (int i = t; i < HID_*9; i += 256) wsh[i] = dww[i];
    for (int i = t; i < HID_*H_; i += 256) wexp_sh[i] = wexp[i];
    if (t < 2*HID_) absh[t] = g_ab1[t];
    __syncthreads();
    const float* a0b = g_attn0 + (size_t)b*H_*NN_;
    for (int idx = t; idx < 340; idx += 256){
        int iy = idx / 34, ix = idx - iy*34;
        int gy = y0 + iy - 1, gx = x0 + ix - 1;
        float* drow = &dsh[idx*37];
        if (gy >= 0 && gy < N_ && gx >= 0 && gx < N_){
            int pp = gy*N_ + gx;
            float av[H_];
            #pragma unroll
            for (int i = 0; i < H_; i++) av[i] = a0b[(size_t)i*NN_ + pp];
            #pragma unroll
            for (int ch = 0; ch < HID_; ch++){
                float a = 0.f;
                #pragma unroll
                for (int i = 0; i < H_; i++) a += wexp_sh[ch*H_ + i] * av[i];
                drow[ch] = clamp6(absh[ch]*a + absh[HID_+ch]);
            }
        } else {
            #pragma unroll
            for (int ch = 0; ch < HID_; ch++) drow[ch] = 0.f;
        }
    }
    __syncthreads();
    int lx = t & 31, ly = t >> 5;
    int gy = y0 + ly, gx = x0 + lx;
    if (gy >= N_ || gx >= N_) return;
    float4* op = (float4*)(g_bbi + ((size_t)b*NN_ + gy*N_ + gx)*HID_);
    #pragma unroll
    for (int chg = 0; chg < 9; chg++){
        float4 o4;
        float* po = (float*)&o4;
        #pragma unroll
        for (int j = 0; j < 4; j++){
            int ch = chg*4 + j;
            float acc = 0.f;
            #pragma unroll
            for (int ky = 0; ky < 3; ky++)
                #pragma unroll
                for (int kx = 0; kx < 3; kx++)
                    acc += wsh[ch*9 + ky*3 + kx] *
                           dsh[((ly+ky)*34 + lx+kx)*37 + ch];
            po[j] = acc;
        }
        op[chg] = o4;
    }
}

// ---- conv_pro 36->12 (bn2 on load): g_bbi -> g_ci + bn3 stats fused --------
__global__ __launch_bounds__(256)
void k_conv_pro(const float* __restrict__ wpro){
    __shared__ float wsh[H_*HID_];
    __shared__ float absh[2*HID_];
    __shared__ float red[2*H_];
    int t = threadIdx.x;
    for (int i = t; i < H_*HID_; i += 256) wsh[i] = wpro[i];
    if (t < 2*HID_) absh[t] = g_ab2[t];
    if (t < 2*H_) red[t] = 0.f;
    __syncthreads();
    float s[H_], q[H_];
    #pragma unroll
    for (int o = 0; o < H_; o++){ s[o] = 0.f; q[o] = 0.f; }
    for (int p = blockIdx.x*256 + t; p < P_; p += gridDim.x*256){
        const float4* in = (const float4*)(g_bbi + (size_t)p*HID_);
        float acc[H_];
        #pragma unroll
        for (int o = 0; o < H_; o++) acc[o] = 0.f;
        #pragma unroll
        for (int ig = 0; ig < 9; ig++){
            float4 v4 = in[ig];
            float vv[4];
            vv[0] = clamp6(absh[ig*4+0]*v4.x + absh[HID_+ig*4+0]);
            vv[1] = clamp6(absh[ig*4+1]*v4.y + absh[HID_+ig*4+1]);
            vv[2] = clamp6(absh[ig*4+2]*v4.z + absh[HID_+ig*4+2]);
            vv[3] = clamp6(absh[ig*4+3]*v4.w + absh[HID_+ig*4+3]);
            #pragma unroll
            for (int o = 0; o < H_; o++){
                acc[o] += wsh[o*HID_ + ig*4+0]*vv[0] + wsh[o*HID_ + ig*4+1]*vv[1]
                        + wsh[o*HID_ + ig*4+2]*vv[2] + wsh[o*HID_ + ig*4+3]*vv[3];
            }
        }
        float4* op = (float4*)(g_ci + (size_t)p*H_);
        op[0] = make_float4(acc[0], acc[1], acc[2],  acc[3]);
        op[1] = make_float4(acc[4], acc[5], acc[6],  acc[7]);
        op[2] = make_float4(acc[8], acc[9], acc[10], acc[11]);
        #pragma unroll
        for (int o = 0; o < H_; o++){ s[o] += acc[o]; q[o] += acc[o]*acc[o]; }
    }
    int lane = t & 31;
    #pragma unroll
    for (int o = 0; o < H_; o++){
        float ws = wredsum(s[o]), wq = wredsum(q[o]);
        if (lane == 0){
            atomicAdd(&red[o],    ws);
            atomicAdd(&red[H_+o], wq);
        }
    }
    __syncthreads();
    if (t < 2*H_) atomicAdd(&g_s3[t], red[t]);
}

// ---- z = bn3(c) + a0 -> g_c planes, + z stats ------------------------------
__global__ __launch_bounds__(256)
void k_z(){
    __shared__ float absh[2*H_];
    __shared__ float red[2*H_];
    int t = threadIdx.x;
    if (t < 2*H_){ absh[t] = g_ab3[t]; red[t] = 0.f; }
    __syncthreads();
    float s[H_], q[H_];
    #pragma unroll
    for (int o = 0; o < H_; o++){ s[o] = 0.f; q[o] = 0.f; }
    for (int p = blockIdx.x*256 + t; p < P_; p += gridDim.x*256){
        int b = p / NN_, pp = p - b*NN_;
        const float* cin = g_ci + (size_t)p*H_;
        const float* a0  = g_attn0 + (size_t)b*H_*NN_ + pp;
        float* zo = g_c + (size_t)b*H_*NN_ + pp;
        #pragma unroll
        for (int ch = 0; ch < H_; ch++){
            float z = absh[ch]*cin[ch] + absh[H_+ch] + a0[(size_t)ch*NN_];
            zo[(size_t)ch*NN_] = z;
            s[ch] += z; q[ch] += z*z;
        }
    }
    int lane = t & 31;
    #pragma unroll
    for (int ch = 0; ch < H_; ch++){
        float ws = wredsum(s[ch]), wq = wredsum(q[ch]);
        if (lane == 0){
            atomicAdd(&red[ch],     ws);
            atomicAdd(&red[H_+ch],  wq);
        }
    }
    __syncthreads();
    if (t < 2*H_) atomicAdd(&g_s4[t], red[t]);
}

// --- attn @ v (abn affine inline); also writes final attn into d_out --------
__global__ __launch_bounds__(256)
void k_av(float* __restrict__ outattn){
    __shared__ float vsh[197][32];
    __shared__ float ash[8][197];
    int bh = blockIdx.y, tile = blockIdx.x;
    int ch = bh % H_;
    float al = g_ab4[ch], be = g_ab4[H_+ch];
    const float* vb = g_v + (size_t)bh * N_ * HD_;
    for (int idx = threadIdx.x; idx < N_*HD_; idx += 256)
        vsh[idx >> 5][idx & 31] = vb[idx];
    __syncthreads();
    int w = threadIdx.x >> 5, lane = threadIdx.x & 31;
    int rrow = tile*8 + w;
    if (rrow >= N_) return;
    size_t rbase = ((size_t)bh * N_ + rrow) * N_;
    const float* arow = g_c + rbase;
    if (outattn){
        float* orow = outattn + rbase;
        for (int m = lane; m < N_; m += 32){
            float v = al * arow[m] + be;
            ash[w][m] = v;
            orow[m] = v;
        }
    } else {
        for (int m = lane; m < N_; m += 32) ash[w][m] = al * arow[m] + be;
    }
    __syncwarp();
    float acc = 0.f;
    #pragma unroll 8
    for (int m = 0; m < N_; m++)
        acc += ash[w][m] * vsh[m][lane];
    int b = bh / H_, h = bh % H_;
    g_o[((size_t)b*N_ + rrow)*C_ + h*HD_ + lane] = acc;
}

// ------------------------------- launch -------------------------------------
extern "C" void kernel_launch(void* const* d_in, const int* in_sizes, int n_in,
                              void* d_out, int out_size){
    const float* x        = (const float*)d_in[0];
    const float* ln1_g    = (const float*)d_in[1];
    const float* ln1_b    = (const float*)d_in[2];
    const float* qkv_w    = (const float*)d_in[3];
    const float* conv_exp = (const float*)d_in[4];
    const float* bn1_g    = (const float*)d_in[5];
    const float* bn1_b    = (const float*)d_in[6];
    const float* dw_w     = (const float*)d_in[7];
    const float* bn2_g    = (const float*)d_in[8];
    const float* bn2_b    = (const float*)d_in[9];
    const float* conv_pro = (const float*)d_in[10];
    const float* bn3_g    = (const float*)d_in[11];
    const float* bn3_b    = (const float*)d_in[12];
    const float* abn_g    = (const float*)d_in[13];
    const float* abn_b    = (const float*)d_in[14];
    const float* proj_w   = (const float*)d_in[15];
    const float* proj_b   = (const float*)d_in[16];
    const float* ln2_g    = (const float*)d_in[17];
    const float* ln2_b    = (const float*)d_in[18];
    const float* fc1_w    = (const float*)d_in[19];
    const float* fc1_b    = (const float*)d_in[20];
    const float* fc2_w    = (const float*)d_in[21];
    const float* fc2_b    = (const float*)d_in[22];
    const float* scale_ch = (const float*)d_in[23];

    float* out      = (float*)d_out;
    float* out_attn = (out_size >= XSZ_ + ASZ_) ? (out + XSZ_) : nullptr;

    float *p_h, *p_o, *p_x1, *p_h2, *p_m1, *p_bbi, *p_ci;
    float *p_s2, *p_s3, *p_s4, *p_ab2, *p_ab3, *p_ab4;
    cudaGetSymbolAddress((void**)&p_h,   g_h);
    cudaGetSymbolAddress((void**)&p_o,   g_o);
    cudaGetSymbolAddress((void**)&p_x1,  g_x1);
    cudaGetSymbolAddress((void**)&p_h2,  g_h2);
    cudaGetSymbolAddress((void**)&p_m1,  g_m1);
    cudaGetSymbolAddress((void**)&p_bbi, g_bbi);
    cudaGetSymbolAddress((void**)&p_ci,  g_ci);
    cudaGetSymbolAddress((void**)&p_s2,  g_s2);
    cudaGetSymbolAddress((void**)&p_s3,  g_s3);
    cudaGetSymbolAddress((void**)&p_s4,  g_s4);
    cudaGetSymbolAddress((void**)&p_ab2, g_ab2);
    cudaGetSymbolAddress((void**)&p_ab3, g_ab3);
    cudaGetSymbolAddress((void**)&p_ab4, g_ab4);

    const int DW_SMEM = 340*37*4;   // 50320 B dynamic
    cudaFuncSetAttribute(k_dw, cudaFuncAttributeMaxDynamicSharedMemorySize, DW_SMEM);

    // ncu capture slot (4th launch) = k_cov (new register-pressure risk)
    k_ln<<<ROWS_, 128>>>(x, ln1_g, ln1_b, p_h, 1);
    gemm_k<V_QKV><<<dim3(18, 50), 256>>>(p_h, qkv_w, nullptr, nullptr, nullptr,
                                         nullptr, ROWS_, 1152, 384);
    k_attn_softmax<<<dim3(25, B_*H_), 256>>>();
    k_cov<<<1184, 256>>>();
    k_fin_bn1<<<1, 64>>>(conv_exp, bn1_g, bn1_b);
    k_dw<<<dim3(175, B_), 256, DW_SMEM>>>(dw_w, conv_exp);
    k_stats<HID_><<<1184, 288>>>((const float4*)p_bbi, p_s2);
    k_fin_bn<HID_><<<1, 64>>>(bn2_g, bn2_b, p_s2, p_ab2);
    k_conv_pro<<<1184, 256>>>(conv_pro);           // bn3 stats fused
    k_fin_bn<H_><<<1, 32>>>(bn3_g, bn3_b, p_s3, p_ab3);
    k_z<<<1184, 256>>>();
    k_fin_bn<H_><<<1, 32>>>(abn_g, abn_b, p_s4, p_ab4);
    // attn @ v (abn inline, writes out_attn), proj + residual
    k_av<<<dim3(25, B_*H_), 256>>>(out_attn);
    gemm_k<V_PROJ><<<dim3(6, 50), 256>>>(p_o, proj_w, proj_b, nullptr, x,
                                         p_x1, ROWS_, 384, 384);
    // MLP
    k_ln<<<ROWS_, 128>>>(p_x1, ln2_g, ln2_b, p_h2, 0);
    gemm_k<V_FC1><<<dim3(24, 50), 256>>>(p_h2, fc1_w, fc1_b, nullptr, nullptr,
                                         p_m1, ROWS_, MLPH_, 384);
    gemm_k<V_FC2><<<dim3(6, 50), 256>>>(p_m1, fc2_w, fc2_b, scale_ch, p_x1,
                                        out, ROWS_, 384, MLPH_);
}